// round 16
// baseline (speedup 1.0000x reference)
#include <cuda_runtime.h>
#include <cuda_bf16.h>
#include <math.h>

#define Hdim 256
#define Wdim 256
#define HW   65536
#define CC   12
#define BB   8
#define BC   96
#define SENT 600        // sentinel: 600^2 = 360000 > max real d^2 (130050)

#define PQ_SCALE 65535.0f
#define PQ_INV   (1.0f / 65535.0f)

#define NVERT  (BC * 2)          // 192 vertical-scan blocks
#define NSOFT  (BB * 32)         // 256 softmax blocks
#define NPRE   (NVERT + NSOFT)   // 448 producer blocks
#define NMAIN  (BC * Hdim / 4)   // 6144 consumer blocks

// Scratch (device globals; no allocation allowed).
// All counters/accumulators zero at module load and reset to zero by the
// final block each run -> every graph replay sees identical state.
__device__ unsigned short g_vU[BC * HW]; // up-scan:  dist | (fg<<15)
__device__ unsigned short g_vD[BC * HW]; // down-scan: dist
__device__ unsigned short g_p [BC * HW]; // quantized softmax probs
__device__ int   g_hasfg[BC];            // plain stores (covered by vrdy fence)
__device__ int   g_vrdy [BC];            // vert readiness: ==2 when both dirs done
__device__ int   g_srdy [BB * 32];       // softmax readiness per (b, rowgroup)
__device__ float g_minmax[BC * 2];       // (min<=0, max>=0) per bc -- atomic
__device__ float g_dsum  [BC * 3];       // (sum d, sum d^2, sum p*d) -- atomic
__device__ float g_sums  [BC * 2];       // (sum p, sum p^2) -- atomic
__device__ unsigned g_ctr;               // main-part completion counter

__device__ __forceinline__ float atomicMinFloat(float* a, float v) {
    return (v >= 0.0f)
        ? __int_as_float(atomicMin((int*)a, __float_as_int(v)))
        : __uint_as_float(atomicMax((unsigned*)a, __float_as_uint(v)));
}
__device__ __forceinline__ float atomicMaxFloat(float* a, float v) {
    return (v >= 0.0f)
        ? __int_as_float(atomicMax((int*)a, __float_as_int(v)))
        : __uint_as_float(atomicMin((unsigned*)a, __float_as_uint(v)));
}

// ---------------------------------------------------------------------------
// ONE kernel, three block roles (producers first => wave-1 resident => no
// deadlock: 448 producers < wave-1 capacity ~1184 blocks):
//  [0,192):    vertical 1D distance scans ((bc,dir) split)      -> g_vrdy
//  [192,448):  softmax; p as u16; Sp/Sp2 atomics                -> g_srdy
//  [448,6592): horizontal EDT search + moments (spins on flags)
// ---------------------------------------------------------------------------
__global__ void __launch_bounds__(256) k_all(const int* __restrict__ targets,
                                             const float* __restrict__ logits,
                                             float* __restrict__ out) {
    // main-part shared memory (reserved by all blocks; 8 blocks/SM OK)
    __shared__ __align__(16) float sm[8][768];
    __shared__ float red[5][8];

    const int bid = blockIdx.x;

    if (bid < NVERT) {
        // ---------------- vertical scans ----------------
        const int bc  = bid >> 1;
        const int dir = bid & 1;
        const int b   = bc / CC, c = bc % CC;
        const int w   = threadIdx.x;
        const int* tb = targets + b * HW;

        if (dir == 0) {
            unsigned short* V = g_vU + bc * HW;
            int upP = -100000, upN = -100000;
            int anyfg = 0;
            #pragma unroll 16
            for (int h = 0; h < Hdim; ++h) {
                const int fg = (tb[h * Wdim + w] == c);
                anyfg |= fg;
                if (!fg) upP = h;
                else     upN = h;
                const int d = fg ? min(h - upP, SENT) : min(h - upN, SENT);
                V[h * Wdim + w] = (unsigned short)(d | (fg << 15));
            }
            const int blkfg = __syncthreads_or(anyfg);
            if (w == 0) g_hasfg[bc] = blkfg;
        } else {
            unsigned short* V = g_vD + bc * HW;
            int dnP = 100000, dnN = 100000;
            #pragma unroll 16
            for (int h = Hdim - 1; h >= 0; --h) {
                const int fg = (tb[h * Wdim + w] == c);
                if (!fg) dnP = h;
                else     dnN = h;
                const int d = fg ? min(dnP - h, SENT) : min(dnN - h, SENT);
                V[h * Wdim + w] = (unsigned short)d;
            }
        }
        __syncthreads();
        __threadfence();                       // release data
        if (threadIdx.x == 0) atomicAdd(&g_vrdy[bc], 1);
        return;
    }

    if (bid < NPRE) {
        // ---------------- softmax + Sp/Sp2 ----------------
        const int blkp = bid - NVERT;          // b*32 + rowgroup
        const int b    = blkp >> 5;
        const int h0   = (blkp & 31) * 8;
        const int w    = threadIdx.x;

        float aS[CC], aP2[CC];
        #pragma unroll
        for (int c = 0; c < CC; ++c) { aS[c] = 0.0f; aP2[c] = 0.0f; }

        const int boff = b * CC * HW;
        for (int r = 0; r < 8; ++r) {
            const int pix = (h0 + r) * Wdim + w;
            float l[CC];
            float mxl = -1e30f;
            #pragma unroll
            for (int c = 0; c < CC; ++c) {
                l[c] = logits[boff + c * HW + pix];
                mxl = fmaxf(mxl, l[c]);
            }
            float s = 0.0f;
            #pragma unroll
            for (int c = 0; c < CC; ++c) { l[c] = __expf(l[c] - mxl); s += l[c]; }
            const float rs = 1.0f / s;
            #pragma unroll
            for (int c = 0; c < CC; ++c) {
                const float p = l[c] * rs;
                g_p[boff + c * HW + pix] =
                    (unsigned short)__float2uint_rn(p * PQ_SCALE);
                aS [c] += p;
                aP2[c] = fmaf(p, p, aP2[c]);
            }
        }

        #pragma unroll
        for (int c = 0; c < CC; ++c) {
            #pragma unroll
            for (int o = 16; o; o >>= 1) {
                aS [c] += __shfl_xor_sync(0xffffffffu, aS [c], o);
                aP2[c] += __shfl_xor_sync(0xffffffffu, aP2[c], o);
            }
        }
        float (*sred)[8] = (float (*)[8])sm;   // reuse main smem
        const int lane = w & 31, wi = w >> 5;
        if (lane == 0) {
            #pragma unroll
            for (int c = 0; c < CC; ++c) {
                sred[c * 2 + 0][wi] = aS [c];
                sred[c * 2 + 1][wi] = aP2[c];
            }
        }
        __syncthreads();
        if (w < 24) {
            float acc = 0.0f;
            #pragma unroll
            for (int i = 0; i < 8; ++i) acc += sred[w][i];
            atomicAdd(&g_sums[(b * CC + (w >> 1)) * 2 + (w & 1)], acc);
        }
        __syncthreads();
        __threadfence();                       // release p data
        if (w == 0) atomicExch(&g_srdy[blkp], 1);
        return;
    }

    // ---------------- main: horizontal EDT + moments ----------------
    const int m    = bid - NPRE;               // [0, NMAIN)
    const int row0 = m << 2;                   // first of 4 rows (same bc)
    const int bc   = row0 >> 8;
    const int rg   = (m >> 1) & 31;            // rowgroup of 8 = (row0&255)/8
    const int b    = bc / CC;
    const int j    = threadIdx.x;

    // wait for producers (thread 0 polls, others park at the barrier)
    if (j == 0) {
        while (*(volatile int*)&g_vrdy[bc] < 2)         __nanosleep(128);
        while (*(volatile int*)&g_srdy[b * 32 + rg] == 0) __nanosleep(128);
    }
    __syncthreads();
    __threadfence();                           // acquire

    // vectorized pad fill: pads [0,256) and [512,768) of each of 8 arrays
    {
        float4* p4 = (float4*)sm;
        const float4 big = make_float4(1.0e9f, 1.0e9f, 1.0e9f, 1.0e9f);
        #pragma unroll
        for (int i = 0; i < 4; ++i) {
            const int t   = j + i * 256;       // 0..1023
            const int seg = t >> 7;
            const int off = t & 127;
            p4[seg * 192 + (off < 64 ? off : off + 64)] = big;
        }
    }

    int   fgr [4];
    float fsqr[4], pv[4];
    #pragma unroll
    for (int r = 0; r < 4; ++r) {
        const int gi = (row0 + r) * Wdim + j;
        const unsigned vu = g_vU[gi];
        const unsigned vd = g_vD[gi];
        const int   fgk = (int)(vu >> 15);
        const float dd  = (float)min((int)(vu & 0x7fffu), (int)vd);
        const float sq  = dd * dd;
        sm[r * 2 + 0][256 + j] = fgk ? sq : 0.0f;
        sm[r * 2 + 1][256 + j] = fgk ? 0.0f : sq;
        fgr [r] = fgk;
        fsqr[r] = sq;
        pv  [r] = (float)g_p[gi] * PQ_INV;
    }
    const int hf = g_hasfg[bc];
    __syncthreads();

    float mn = 0.0f, mx = 0.0f, sd = 0.0f, sd2 = 0.0f, spd = 0.0f;
    #pragma unroll
    for (int r = 0; r < 4; ++r) {
        const float* s = &sm[r * 2 + (fgr[r] ? 0 : 1)][256 + j];
        float best = fsqr[r];
        float rr = 1.0f, rr1 = 4.0f, f4 = 4.0f;
        #pragma unroll 1
        for (int t = 1; t < 256; t += 2) {
            if (rr >= best) break;
            const float a  = fminf(rr  + s[-t],     rr  + s[t]);
            const float b2 = fminf(rr1 + s[-t - 1], rr1 + s[t + 1]);
            best = fminf(best, fminf(a, b2));
            rr  += f4 + 4.0f;
            rr1 += f4 + 8.0f;
            f4  += 8.0f;
        }
        float dt = fgr[r] ? -sqrtf(best) : sqrtf(best);
        if (!hf) dt = 0.0f;
        mn  = fminf(mn, dt);
        mx  = fmaxf(mx, dt);
        sd  += dt;
        sd2 += dt * dt;
        spd = fmaf(pv[r], dt, spd);
    }

    #pragma unroll
    for (int o = 16; o; o >>= 1) {
        mn  = fminf(mn, __shfl_xor_sync(0xffffffffu, mn, o));
        mx  = fmaxf(mx, __shfl_xor_sync(0xffffffffu, mx, o));
        sd  += __shfl_xor_sync(0xffffffffu, sd,  o);
        sd2 += __shfl_xor_sync(0xffffffffu, sd2, o);
        spd += __shfl_xor_sync(0xffffffffu, spd, o);
    }
    const int wid = j >> 5, lane = j & 31;
    if (lane == 0) {
        red[0][wid] = mn; red[1][wid] = mx;
        red[2][wid] = sd; red[3][wid] = sd2; red[4][wid] = spd;
    }
    __syncthreads();
    if (j == 0) {
        mn = red[0][0]; mx = red[1][0]; sd = red[2][0]; sd2 = red[3][0]; spd = red[4][0];
        #pragma unroll
        for (int i = 1; i < 8; ++i) {
            mn  = fminf(mn, red[0][i]);
            mx  = fmaxf(mx, red[1][i]);
            sd  += red[2][i];
            sd2 += red[3][i];
            spd += red[4][i];
        }
        atomicMinFloat(&g_minmax[bc * 2],     mn);
        atomicMaxFloat(&g_minmax[bc * 2 + 1], mx);
        atomicAdd(&g_dsum[bc * 3],     sd);
        atomicAdd(&g_dsum[bc * 3 + 1], sd2);
        atomicAdd(&g_dsum[bc * 3 + 2], spd);
    }

    // ---- last-main-block-done: compute loss, reset ALL state ----
    __threadfence();
    __shared__ unsigned done;
    if (j == 0) done = atomicAdd(&g_ctr, 1u);
    __syncthreads();
    if (done == NMAIN - 1) {
        __threadfence();
        __shared__ float sfin[BC];
        if (j < BC) {
            const float dmin = g_minmax[j * 2];
            const float dmax = g_minmax[j * 2 + 1];
            const float inv  = 1.0f / (dmax - dmin + 1e-8f);
            const float Sd   = g_dsum[j * 3];
            const float Sd2  = g_dsum[j * 3 + 1];
            const float Spd  = g_dsum[j * 3 + 2];
            const float Sp   = g_sums[j * 2];
            const float Sp2  = g_sums[j * 2 + 1];
            const float I  = inv * (Spd - dmin * Sp);
            const float D2 = inv * inv * (Sd2 - 2.0f * dmin * Sd + 65536.0f * dmin * dmin);
            sfin[j] = 1.0f - 2.0f * I / (Sp2 + D2 + 1e-6f);
        }
        __syncthreads();
        if (j == 0) {
            float acc = 0.0f;
            #pragma unroll
            for (int i = 0; i < BC; ++i) acc += sfin[i];
            out[0] = acc / (float)BC;
        }
        // reset everything for the next graph replay (full coverage)
        for (int k = j; k < BC * 2;  k += 256) g_minmax[k] = 0.0f;
        for (int k = j; k < BC * 3;  k += 256) g_dsum[k]   = 0.0f;
        for (int k = j; k < BC * 2;  k += 256) g_sums[k]   = 0.0f;
        for (int k = j; k < BC;      k += 256) g_vrdy[k]   = 0;
        for (int k = j; k < BB * 32; k += 256) g_srdy[k]   = 0;
        if (j == 0) g_ctr = 0u;
    }
}

extern "C" void kernel_launch(void* const* d_in, const int* in_sizes, int n_in,
                              void* d_out, int out_size) {
    const float* logits  = (const float*)d_in[0];
    const int*   targets = (const int*)d_in[1];
    float* out = (float*)d_out;

    k_all<<<NPRE + NMAIN, 256>>>(targets, logits, out);
}

// round 17
// speedup vs baseline: 1.2070x; 1.2070x over previous
#include <cuda_runtime.h>
#include <cuda_bf16.h>
#include <math.h>

#define Hdim 256
#define Wdim 256
#define HW   65536
#define CC   12
#define BB   8
#define BC   96
#define SENT 600        // sentinel: > max possible distance (360.6)

#define PQ_SCALE 65535.0f
#define PQ_INV   (1.0f / 65535.0f)

#define NVERT (BC * 4)           // 4 roles per (b,c): (up,dn) x (half0,half1)
#define NSOFT (BB * 32)

// Scratch (device globals; no allocation allowed).
__device__ unsigned short g_vU[BC * HW]; // half-local up-scan: dist | (fg<<15)
__device__ unsigned short g_vD[BC * HW]; // half-local down-scan: dist
__device__ unsigned g_bU[BC * Wdim];     // at row 127: distToBg | distToFg<<16 (upward)
__device__ unsigned g_bD[BC * Wdim];     // at row 128: distToBg | distToFg<<16 (downward)
__device__ unsigned short g_p [BC * HW]; // quantized softmax probs
__device__ int   g_hasfg[BC * 2];        // per half, plain stores
__device__ float g_minmax[BC * 2];       // (min<=0, max>=0) per bc -- atomic
__device__ float g_dsum  [BC * 3];       // (sum d, sum d^2, sum p*d) -- atomic
__device__ float g_sums  [BC * 2];       // (sum p, sum p^2) -- atomic
__device__ unsigned g_ctr;               // k_main completion counter

__device__ __forceinline__ float atomicMinFloat(float* a, float v) {
    return (v >= 0.0f)
        ? __int_as_float(atomicMin((int*)a, __float_as_int(v)))
        : __uint_as_float(atomicMax((unsigned*)a, __float_as_uint(v)));
}
__device__ __forceinline__ float atomicMaxFloat(float* a, float v) {
    return (v >= 0.0f)
        ? __int_as_float(atomicMax((int*)a, __float_as_int(v)))
        : __uint_as_float(atomicMin((unsigned*)a, __float_as_uint(v)));
}

// ---------------------------------------------------------------------------
// K1: 640 blocks.
//  [0,384): segmented vertical scans. Role = (bc, dir, half); each block
//    scans 128 rows of its half (serial chain HALVED vs full-column scan).
//    Up-scan of half0 also emits the row-127 boundary pair (dist to nearest
//    bg / fg upward); down-scan of half1 emits the row-128 pair. k_main
//    folds the carry, so the combined vertical distance stays EXACT.
//  [384,640): softmax over C per pixel; p as u16; Sp/Sp2 atomics.
// ---------------------------------------------------------------------------
__global__ void __launch_bounds__(256) k_pre(const int* __restrict__ targets,
                                             const float* __restrict__ logits) {
    const int bid = blockIdx.x;
    if (bid < NVERT) {
        const int bc   = bid >> 2;
        const int dir  = (bid >> 1) & 1;
        const int half = bid & 1;
        const int b = bc / CC, c = bc % CC;
        const int w = threadIdx.x;
        const int s = half << 7;               // first row of the half
        const int* tb = targets + b * HW;

        if (dir == 0) {
            // up-scan of rows [s, s+128)
            unsigned short* V = g_vU + bc * HW;
            int upP = -100000;   // last bg row seen
            int upN = -100000;   // last fg row seen
            int anyfg = 0;
            #pragma unroll 16
            for (int i = 0; i < 128; ++i) {
                const int h = s + i;
                const int fg = (tb[h * Wdim + w] == c);
                anyfg |= fg;
                if (!fg) upP = h;
                else     upN = h;
                const int d = fg ? min(h - upP, SENT) : min(h - upN, SENT);
                V[h * Wdim + w] = (unsigned short)(d | (fg << 15));
            }
            if (half == 0) {
                const unsigned dBg = (unsigned)min(127 - upP, SENT);
                const unsigned dFg = (unsigned)min(127 - upN, SENT);
                g_bU[bc * Wdim + w] = dBg | (dFg << 16);
            }
            const int blkfg = __syncthreads_or(anyfg);
            if (w == 0) g_hasfg[bc * 2 + half] = blkfg;
        } else {
            // down-scan of rows [s+127 .. s]
            unsigned short* V = g_vD + bc * HW;
            int dnP = 100000, dnN = 100000;
            #pragma unroll 16
            for (int i = 127; i >= 0; --i) {
                const int h = s + i;
                const int fg = (tb[h * Wdim + w] == c);
                if (!fg) dnP = h;
                else     dnN = h;
                const int d = fg ? min(dnP - h, SENT) : min(dnN - h, SENT);
                V[h * Wdim + w] = (unsigned short)d;
            }
            if (half == 1) {
                const unsigned dBg = (unsigned)min(dnP - 128, SENT);
                const unsigned dFg = (unsigned)min(dnN - 128, SENT);
                g_bD[bc * Wdim + w] = dBg | (dFg << 16);
            }
        }
    } else {
        // ---------------- softmax + Sp/Sp2 (unchanged) ----------------
        const int blkp = bid - NVERT;          // b*32 + rowgroup
        const int b    = blkp >> 5;
        const int h0   = (blkp & 31) * 8;
        const int w    = threadIdx.x;

        float aS[CC], aP2[CC];
        #pragma unroll
        for (int c = 0; c < CC; ++c) { aS[c] = 0.0f; aP2[c] = 0.0f; }

        const int boff = b * CC * HW;
        for (int r = 0; r < 8; ++r) {
            const int pix = (h0 + r) * Wdim + w;
            float l[CC];
            float mxl = -1e30f;
            #pragma unroll
            for (int c = 0; c < CC; ++c) {
                l[c] = logits[boff + c * HW + pix];
                mxl = fmaxf(mxl, l[c]);
            }
            float sum = 0.0f;
            #pragma unroll
            for (int c = 0; c < CC; ++c) { l[c] = __expf(l[c] - mxl); sum += l[c]; }
            const float rs = 1.0f / sum;
            #pragma unroll
            for (int c = 0; c < CC; ++c) {
                const float p = l[c] * rs;
                g_p[boff + c * HW + pix] =
                    (unsigned short)__float2uint_rn(p * PQ_SCALE);
                aS [c] += p;
                aP2[c] = fmaf(p, p, aP2[c]);
            }
        }

        #pragma unroll
        for (int c = 0; c < CC; ++c) {
            #pragma unroll
            for (int o = 16; o; o >>= 1) {
                aS [c] += __shfl_xor_sync(0xffffffffu, aS [c], o);
                aP2[c] += __shfl_xor_sync(0xffffffffu, aP2[c], o);
            }
        }
        __shared__ float sred[24][8];
        const int lane = w & 31, wi = w >> 5;
        if (lane == 0) {
            #pragma unroll
            for (int c = 0; c < CC; ++c) {
                sred[c * 2 + 0][wi] = aS [c];
                sred[c * 2 + 1][wi] = aP2[c];
            }
        }
        __syncthreads();
        if (w < 24) {
            float acc = 0.0f;
            #pragma unroll
            for (int i = 0; i < 8; ++i) acc += sred[w][i];
            atomicAdd(&g_sums[(b * CC + (w >> 1)) * 2 + (w & 1)], acc);
        }
    }
}

// ---------------------------------------------------------------------------
// K2: horizontal exact min-plus, 4 rows/block (R15-proven), plus boundary
// carry fold at fill: d = min(up_local, dn_local, carry) -- exact vertical
// distance across the segment split. Padded smem -> no index clamping;
// 2 radii per exit check. Last block computes loss + resets accumulators.
// ---------------------------------------------------------------------------
__global__ void __launch_bounds__(256) k_main(float* __restrict__ out) {
    const int row0 = blockIdx.x << 2;      // 4 rows, same bc, same half (128|4)
    const int bc   = row0 >> 8;
    const int j    = threadIdx.x;

    __shared__ __align__(16) float sm[8][768];
    // vectorized pad fill
    {
        float4* p4 = (float4*)sm;
        const float4 big = make_float4(1.0e9f, 1.0e9f, 1.0e9f, 1.0e9f);
        #pragma unroll
        for (int i = 0; i < 4; ++i) {
            const int t   = j + i * 256;
            const int seg = t >> 7;
            const int off = t & 127;
            p4[seg * 192 + (off < 64 ? off : off + 64)] = big;
        }
    }

    const int hrow0 = row0 & 255;              // image row of r=0
    const bool lower = hrow0 >= 128;
    const unsigned bnd = lower ? g_bU[bc * Wdim + j] : g_bD[bc * Wdim + j];
    const int base0 = lower ? (hrow0 - 127) : (128 - hrow0);

    int   fgr [4];
    float fsqr[4], pv[4];
    #pragma unroll
    for (int r = 0; r < 4; ++r) {
        const int gi = (row0 + r) * Wdim + j;
        const unsigned vu = g_vU[gi];
        const unsigned vd = g_vD[gi];
        const int fgk = (int)(vu >> 15);
        const int cb  = fgk ? (int)(bnd & 0xffffu) : (int)(bnd >> 16);
        const int carry = (lower ? base0 + r : base0 - r) + cb;
        const int di  = min(min((int)(vu & 0x7fffu), (int)vd), carry);
        const float dd = (float)di;
        const float sq = dd * dd;
        sm[r * 2 + 0][256 + j] = fgk ? sq : 0.0f;
        sm[r * 2 + 1][256 + j] = fgk ? 0.0f : sq;
        fgr [r] = fgk;
        fsqr[r] = sq;
        pv  [r] = (float)g_p[gi] * PQ_INV;
    }
    const int hf = g_hasfg[bc * 2] | g_hasfg[bc * 2 + 1];
    __syncthreads();

    float mn = 0.0f, mx = 0.0f, sd = 0.0f, sd2 = 0.0f, spd = 0.0f;
    #pragma unroll
    for (int r = 0; r < 4; ++r) {
        const float* s = &sm[r * 2 + (fgr[r] ? 0 : 1)][256 + j];
        float best = fsqr[r];
        float rr = 1.0f, rr1 = 4.0f, f4 = 4.0f;
        #pragma unroll 1
        for (int t = 1; t < 256; t += 2) {
            if (rr >= best) break;
            const float a  = fminf(rr  + s[-t],     rr  + s[t]);
            const float b2 = fminf(rr1 + s[-t - 1], rr1 + s[t + 1]);
            best = fminf(best, fminf(a, b2));
            rr  += f4 + 4.0f;
            rr1 += f4 + 8.0f;
            f4  += 8.0f;
        }
        float dt = fgr[r] ? -sqrtf(best) : sqrtf(best);
        if (!hf) dt = 0.0f;
        mn  = fminf(mn, dt);
        mx  = fmaxf(mx, dt);
        sd  += dt;
        sd2 += dt * dt;
        spd = fmaf(pv[r], dt, spd);
    }

    #pragma unroll
    for (int o = 16; o; o >>= 1) {
        mn  = fminf(mn, __shfl_xor_sync(0xffffffffu, mn, o));
        mx  = fmaxf(mx, __shfl_xor_sync(0xffffffffu, mx, o));
        sd  += __shfl_xor_sync(0xffffffffu, sd,  o);
        sd2 += __shfl_xor_sync(0xffffffffu, sd2, o);
        spd += __shfl_xor_sync(0xffffffffu, spd, o);
    }
    __shared__ float red[5][8];
    const int wid = j >> 5, lane = j & 31;
    if (lane == 0) {
        red[0][wid] = mn; red[1][wid] = mx;
        red[2][wid] = sd; red[3][wid] = sd2; red[4][wid] = spd;
    }
    __syncthreads();
    if (j == 0) {
        mn = red[0][0]; mx = red[1][0]; sd = red[2][0]; sd2 = red[3][0]; spd = red[4][0];
        #pragma unroll
        for (int i = 1; i < 8; ++i) {
            mn  = fminf(mn, red[0][i]);
            mx  = fmaxf(mx, red[1][i]);
            sd  += red[2][i];
            sd2 += red[3][i];
            spd += red[4][i];
        }
        atomicMinFloat(&g_minmax[bc * 2],     mn);
        atomicMaxFloat(&g_minmax[bc * 2 + 1], mx);
        atomicAdd(&g_dsum[bc * 3],     sd);
        atomicAdd(&g_dsum[bc * 3 + 1], sd2);
        atomicAdd(&g_dsum[bc * 3 + 2], spd);
    }

    // ---- last-block-done: compute loss, then reset accumulators ----
    __threadfence();
    __shared__ unsigned done;
    if (j == 0) done = atomicAdd(&g_ctr, 1u);
    __syncthreads();
    if (done == gridDim.x - 1) {
        __threadfence();
        __shared__ float sfin[BC];
        if (j < BC) {
            const float dmin = g_minmax[j * 2];
            const float dmax = g_minmax[j * 2 + 1];
            const float inv  = 1.0f / (dmax - dmin + 1e-8f);
            const float Sd   = g_dsum[j * 3];
            const float Sd2  = g_dsum[j * 3 + 1];
            const float Spd  = g_dsum[j * 3 + 2];
            const float Sp   = g_sums[j * 2];
            const float Sp2  = g_sums[j * 2 + 1];
            const float I  = inv * (Spd - dmin * Sp);
            const float D2 = inv * inv * (Sd2 - 2.0f * dmin * Sd + 65536.0f * dmin * dmin);
            sfin[j] = 1.0f - 2.0f * I / (Sp2 + D2 + 1e-6f);
        }
        __syncthreads();
        if (j == 0) {
            float acc = 0.0f;
            #pragma unroll
            for (int i = 0; i < BC; ++i) acc += sfin[i];
            out[0] = acc / (float)BC;
        }
        for (int k = j; k < BC * 2; k += 256) g_minmax[k] = 0.0f;
        for (int k = j; k < BC * 3; k += 256) g_dsum[k]   = 0.0f;
        for (int k = j; k < BC * 2; k += 256) g_sums[k]   = 0.0f;
        if (j == 0) g_ctr = 0u;
    }
}

extern "C" void kernel_launch(void* const* d_in, const int* in_sizes, int n_in,
                              void* d_out, int out_size) {
    const float* logits  = (const float*)d_in[0];
    const int*   targets = (const int*)d_in[1];
    float* out = (float*)d_out;

    k_pre <<<NVERT + NSOFT, 256>>>(targets, logits);
    k_main<<<BC * Hdim / 4, 256>>>(out);
}